// round 15
// baseline (speedup 1.0000x reference)
#include <cuda_runtime.h>
#include <cuda_fp16.h>
#include <cuda_bf16.h>

#define BB 2
#define NC 128
#define NZ 256
#define NS 2048
#define NX 256
#define KK 4
#define MM (NZ * NX)

#define DTHREADS 1024
#define PXB 2048                         // pixels per block (2 per thread)
#define SPLIT 4                          // channel split factor
#define CHQ (NC / SPLIT)                 // 32 channels per block
#define PTILES (MM / PXB)                // 32 pixel tiles per batch
#define SMEM_BYTES (2 * NS * 16 + NC * 16 + 16)   // 2 ch buffers + pr + params

// fp16 PAIR-packed rf: d_rfp[(b*NC+c)*NS + s] = 8 halves {rf[s,0:4], rf[s+1,0:4]} (16B)
__device__ uint4  d_rfp[BB * NC * NS];
// Partial sums: [quarter][b][pixel] as float4
__device__ float4 d_part[SPLIT * BB * MM];

__global__ void pack_kernel(const float* __restrict__ rf) {
    const int t = blockIdx.x * blockDim.x + threadIdx.x;   // 0 .. BB*NC*NS-1
    if (t >= BB * NC * NS) return;
    const int s = t & (NS - 1);
    const float4* rf4 = (const float4*)rf;
    const float4 y0 = rf4[t];
    const float4 y1 = rf4[t + (s < NS - 1 ? 1 : 0)];
    __half2 h0 = __floats2half2_rn(y0.x, y0.y);
    __half2 h1 = __floats2half2_rn(y0.z, y0.w);
    __half2 h2 = __floats2half2_rn(y1.x, y1.y);
    __half2 h3 = __floats2half2_rn(y1.z, y1.w);
    uint4 v;
    v.x = *(unsigned*)&h0;
    v.y = *(unsigned*)&h1;
    v.z = *(unsigned*)&h2;
    v.w = *(unsigned*)&h3;
    d_rfp[t] = v;
}

extern __shared__ uint4 dyn_smem[];   // [2][NS] channel buffers, then pr, then params

__global__ __launch_bounds__(DTHREADS, 2) void das_kernel(
    const float* __restrict__ g,    // [B, NZ, NX, 3]
    const float* __restrict__ pr,   // [B, NC, 3]
    const float* __restrict__ p)    // [B, 4]
{
    uint4*  buf  = dyn_smem;                                  // 2 x 32KB
    float4* s_pr = (float4*)(dyn_smem + 2 * NS);
    float*  s_pm = (float*)(s_pr + NC);

    const int tid  = threadIdx.x;
    const int quad = blockIdx.x & (SPLIT - 1);
    const int tile = (blockIdx.x / SPLIT) & (PTILES - 1);
    const int bb   = blockIdx.x / (SPLIT * PTILES);

    const int m0 = tile * PXB + tid;
    const int m1 = m0 + DTHREADS;
    const int c0 = quad * CHQ;

    if (tid < NC) {
        const float* q = pr + ((size_t)bb * NC + tid) * 3;
        s_pr[tid] = make_float4(q[0], q[1], q[2], 0.0f);
    }
    if (tid == 0) {
        const float cc = p[bb * 4 + 0];
        const float fs = p[bb * 4 + 1];
        const float t0 = p[bb * 4 + 2];
        s_pm[0] = fs / cc;
        s_pm[1] = fs * t0 / cc;
    }

    const float* gp0 = g + ((size_t)bb * MM + m0) * 3;
    const float* gp1 = g + ((size_t)bb * MM + m1) * 3;
    const float gx0 = gp0[0], gy0 = gp0[1], gz0 = gp0[2];
    const float gx1 = gp1[0], gy1 = gp1[1], gz1 = gp1[2];

    const uint4* __restrict__ rfg = d_rfp + ((size_t)bb * NC + c0) * NS;

    // Stage channel 0; prefetch channel 1 into regs (2 uint4 per thread).
    buf[tid] = rfg[tid];
    buf[tid + DTHREADS] = rfg[tid + DTHREADS];
    uint4 n0 = rfg[NS + tid];
    uint4 n1 = rfg[NS + tid + DTHREADS];
    __syncthreads();   // params + buf0 visible

    const float scale = s_pm[0];
    const float base  = s_pm[1];

    float4 a0 = make_float4(0.f, 0.f, 0.f, 0.f);
    float4 a1 = make_float4(0.f, 0.f, 0.f, 0.f);

    for (int c = 0; c < CHQ; ++c) {
        // Write buffer for channel c+1 (prefetched during iter c-1).
        // Safe: last reads of buf[(c+1)&1] were in iter c-1, ordered by its sync.
        if (c + 1 < CHQ) {
            uint4* dst = buf + ((c + 1) & 1) * NS;
            dst[tid] = n0;
            dst[tid + DTHREADS] = n1;
        }
        // Prefetch channel c+2 (latency spans the whole iteration).
        if (c + 2 < CHQ) {
            const uint4* src = rfg + (size_t)(c + 2) * NS;
            n0 = src[tid];
            n1 = src[tid + DTHREADS];
        }

        const float4 pc = s_pr[c0 + c];
        const uint4* row = buf + (c & 1) * NS;

        // pixel 0
        {
            const float dx = gx0 - pc.x, dy = gy0 - pc.y, dz = gz0 - pc.z;
            const float r2 = fmaf(dx, dx, fmaf(dy, dy, dz * dz));
            float drx; asm("sqrt.approx.f32 %0, %1;" : "=f"(drx) : "f"(r2));
            float s = fmaf(scale, drx + gz0, base);
            s = fminf(fmaxf(s, 0.0f), (float)(NS - 1));
            const float i0f = fminf(floorf(s), (float)(NS - 2));
            const int   i0  = (int)i0f;
            const float w  = s - i0f;
            const float wm = 1.0f - w;
            const uint4 v = row[i0];                 // ONE LDS.128: both taps
            const float2 f0 = __half22float2(*(const __half2*)&v.x);
            const float2 f1 = __half22float2(*(const __half2*)&v.y);
            const float2 f2 = __half22float2(*(const __half2*)&v.z);
            const float2 f3 = __half22float2(*(const __half2*)&v.w);
            a0.x = fmaf(wm, f0.x, fmaf(w, f2.x, a0.x));
            a0.y = fmaf(wm, f0.y, fmaf(w, f2.y, a0.y));
            a0.z = fmaf(wm, f1.x, fmaf(w, f3.x, a0.z));
            a0.w = fmaf(wm, f1.y, fmaf(w, f3.y, a0.w));
        }
        // pixel 1
        {
            const float dx = gx1 - pc.x, dy = gy1 - pc.y, dz = gz1 - pc.z;
            const float r2 = fmaf(dx, dx, fmaf(dy, dy, dz * dz));
            float drx; asm("sqrt.approx.f32 %0, %1;" : "=f"(drx) : "f"(r2));
            float s = fmaf(scale, drx + gz1, base);
            s = fminf(fmaxf(s, 0.0f), (float)(NS - 1));
            const float i0f = fminf(floorf(s), (float)(NS - 2));
            const int   i0  = (int)i0f;
            const float w  = s - i0f;
            const float wm = 1.0f - w;
            const uint4 v = row[i0];
            const float2 f0 = __half22float2(*(const __half2*)&v.x);
            const float2 f1 = __half22float2(*(const __half2*)&v.y);
            const float2 f2 = __half22float2(*(const __half2*)&v.z);
            const float2 f3 = __half22float2(*(const __half2*)&v.w);
            a1.x = fmaf(wm, f0.x, fmaf(w, f2.x, a1.x));
            a1.y = fmaf(wm, f0.y, fmaf(w, f2.y, a1.y));
            a1.z = fmaf(wm, f1.x, fmaf(w, f3.x, a1.z));
            a1.w = fmaf(wm, f1.y, fmaf(w, f3.y, a1.w));
        }

        __syncthreads();   // one barrier per channel; other resident block fills skew
    }

    float4* part = d_part + ((size_t)quad * BB + bb) * MM;
    part[m0] = a0;
    part[m1] = a1;
}

__global__ void combine_kernel(float* __restrict__ out) {
    const int t = blockIdx.x * blockDim.x + threadIdx.x;   // 0 .. BB*MM-1
    if (t >= BB * MM) return;
    const float4 u0 = d_part[t];
    const float4 u1 = d_part[BB * MM + t];
    const float4 u2 = d_part[2 * BB * MM + t];
    const float4 u3 = d_part[3 * BB * MM + t];
    ((float4*)out)[t] = make_float4((u0.x + u1.x) + (u2.x + u3.x),
                                    (u0.y + u1.y) + (u2.y + u3.y),
                                    (u0.z + u1.z) + (u2.z + u3.z),
                                    (u0.w + u1.w) + (u2.w + u3.w));
}

extern "C" void kernel_launch(void* const* d_in, const int* in_sizes, int n_in,
                              void* d_out, int out_size) {
    const float* rf = (const float*)d_in[0];
    const float* g  = (const float*)d_in[1];
    const float* pr = (const float*)d_in[2];
    const float* p  = (const float*)d_in[3];
    float* out = (float*)d_out;

    // Unconditional (idempotent host-side call; not a stream op, no static guard).
    cudaFuncSetAttribute(das_kernel,
                         cudaFuncAttributeMaxDynamicSharedMemorySize, SMEM_BYTES);

    pack_kernel<<<(BB * NC * NS + 255) / 256, 256>>>(rf);

    das_kernel<<<BB * PTILES * SPLIT, DTHREADS, SMEM_BYTES>>>(g, pr, p);

    combine_kernel<<<(BB * MM + 255) / 256, 256>>>(out);
}

// round 16
// speedup vs baseline: 1.4218x; 1.4218x over previous
#include <cuda_runtime.h>
#include <cuda_fp16.h>
#include <cuda_bf16.h>

#define BB 2
#define NC 128
#define NZ 256
#define NS 2048
#define NX 256
#define KK 4
#define MM (NZ * NX)

#define DTHREADS 1024
#define PXT 4                            // pixels per thread
#define PXB (DTHREADS * PXT)             // 4096 pixels per block
#define SPLIT 4                          // channel split factor
#define CHQ (NC / SPLIT)                 // 32 channels per block
#define PTILES (MM / PXB)                // 16 pixel tiles per batch
#define SMEM_BYTES (2 * NS * 16 + NC * 16 + 16)   // 2 ch buffers + pr + params

// fp16 PAIR-packed rf: d_rfp[(b*NC+c)*NS + s] = 8 halves {rf[s,0:4], rf[s+1,0:4]} (16B)
__device__ uint4  d_rfp[BB * NC * NS];
// Partial sums: [quarter][b][pixel] as float4
__device__ float4 d_part[SPLIT * BB * MM];

__global__ void pack_kernel(const float* __restrict__ rf) {
    const int t = blockIdx.x * blockDim.x + threadIdx.x;   // 0 .. BB*NC*NS-1
    if (t >= BB * NC * NS) return;
    const int s = t & (NS - 1);
    const float4* rf4 = (const float4*)rf;
    const float4 y0 = rf4[t];
    const float4 y1 = rf4[t + (s < NS - 1 ? 1 : 0)];
    __half2 h0 = __floats2half2_rn(y0.x, y0.y);
    __half2 h1 = __floats2half2_rn(y0.z, y0.w);
    __half2 h2 = __floats2half2_rn(y1.x, y1.y);
    __half2 h3 = __floats2half2_rn(y1.z, y1.w);
    uint4 v;
    v.x = *(unsigned*)&h0;
    v.y = *(unsigned*)&h1;
    v.z = *(unsigned*)&h2;
    v.w = *(unsigned*)&h3;
    d_rfp[t] = v;
}

extern __shared__ uint4 dyn_smem[];   // [2][NS] channel buffers, then pr, then params

__global__ __launch_bounds__(DTHREADS, 1) void das_kernel(
    const float* __restrict__ g,    // [B, NZ, NX, 3]
    const float* __restrict__ pr,   // [B, NC, 3]
    const float* __restrict__ p)    // [B, 4]
{
    uint4*  buf  = dyn_smem;                                  // 2 x 32KB
    float4* s_pr = (float4*)(dyn_smem + 2 * NS);
    float*  s_pm = (float*)(s_pr + NC);

    const int tid  = threadIdx.x;
    const int quad = blockIdx.x & (SPLIT - 1);
    const int tile = (blockIdx.x / SPLIT) & (PTILES - 1);
    const int bb   = blockIdx.x / (SPLIT * PTILES);

    const int c0 = quad * CHQ;

    if (tid < NC) {
        const float* q = pr + ((size_t)bb * NC + tid) * 3;
        s_pr[tid] = make_float4(q[0], q[1], q[2], 0.0f);
    }
    if (tid == 0) {
        const float cc = p[bb * 4 + 0];
        const float fs = p[bb * 4 + 1];
        const float t0 = p[bb * 4 + 2];
        s_pm[0] = fs / cc;
        s_pm[1] = fs * t0 / cc;
    }

    int   m[PXT];
    float gx[PXT], gy[PXT], gz[PXT];
    #pragma unroll
    for (int j = 0; j < PXT; ++j) {
        m[j] = tile * PXB + j * DTHREADS + tid;
        const float* gp = g + ((size_t)bb * MM + m[j]) * 3;
        gx[j] = gp[0]; gy[j] = gp[1]; gz[j] = gp[2];
    }

    const uint4* __restrict__ rfg = d_rfp + ((size_t)bb * NC + c0) * NS;

    // Stage channel 0; prefetch channel 1 into regs (2 uint4 per thread).
    buf[tid] = rfg[tid];
    buf[tid + DTHREADS] = rfg[tid + DTHREADS];
    uint4 n0 = rfg[NS + tid];
    uint4 n1 = rfg[NS + tid + DTHREADS];
    __syncthreads();   // params + buf0 visible

    const float scale = s_pm[0];
    const float base  = s_pm[1];

    float4 a[PXT];
    #pragma unroll
    for (int j = 0; j < PXT; ++j) a[j] = make_float4(0.f, 0.f, 0.f, 0.f);

    for (int c = 0; c < CHQ; ++c) {
        // Write buffer for channel c+1 (prefetched during iter c-1).
        // Safe: last reads of buf[(c+1)&1] were in iter c-1, ordered by its sync.
        if (c + 1 < CHQ) {
            uint4* dst = buf + ((c + 1) & 1) * NS;
            dst[tid] = n0;
            dst[tid + DTHREADS] = n1;
        }
        // Prefetch channel c+2 (latency spans the whole iteration).
        if (c + 2 < CHQ) {
            const uint4* src = rfg + (size_t)(c + 2) * NS;
            n0 = src[tid];
            n1 = src[tid + DTHREADS];
        }

        const float4 pc = s_pr[c0 + c];
        const uint4* row = buf + (c & 1) * NS;

        #pragma unroll
        for (int j = 0; j < PXT; ++j) {
            const float dx = gx[j] - pc.x, dy = gy[j] - pc.y, dz = gz[j] - pc.z;
            const float r2 = fmaf(dx, dx, fmaf(dy, dy, dz * dz));
            float drx; asm("sqrt.approx.f32 %0, %1;" : "=f"(drx) : "f"(r2));
            float s = fmaf(scale, drx + gz[j], base);
            s = fminf(fmaxf(s, 0.0f), (float)(NS - 1));
            const float i0f = fminf(floorf(s), (float)(NS - 2));
            const int   i0  = (int)i0f;
            const float w  = s - i0f;
            const float wm = 1.0f - w;
            const uint4 v = row[i0];                 // ONE LDS.128: both taps
            const float2 f0 = __half22float2(*(const __half2*)&v.x);
            const float2 f1 = __half22float2(*(const __half2*)&v.y);
            const float2 f2 = __half22float2(*(const __half2*)&v.z);
            const float2 f3 = __half22float2(*(const __half2*)&v.w);
            a[j].x = fmaf(wm, f0.x, fmaf(w, f2.x, a[j].x));
            a[j].y = fmaf(wm, f0.y, fmaf(w, f2.y, a[j].y));
            a[j].z = fmaf(wm, f1.x, fmaf(w, f3.x, a[j].z));
            a[j].w = fmaf(wm, f1.y, fmaf(w, f3.y, a[j].w));
        }

        __syncthreads();   // one barrier per channel
    }

    float4* part = d_part + ((size_t)quad * BB + bb) * MM;
    #pragma unroll
    for (int j = 0; j < PXT; ++j) part[m[j]] = a[j];
}

__global__ void combine_kernel(float* __restrict__ out) {
    const int t = blockIdx.x * blockDim.x + threadIdx.x;   // 0 .. BB*MM-1
    if (t >= BB * MM) return;
    const float4 u0 = d_part[t];
    const float4 u1 = d_part[BB * MM + t];
    const float4 u2 = d_part[2 * BB * MM + t];
    const float4 u3 = d_part[3 * BB * MM + t];
    ((float4*)out)[t] = make_float4((u0.x + u1.x) + (u2.x + u3.x),
                                    (u0.y + u1.y) + (u2.y + u3.y),
                                    (u0.z + u1.z) + (u2.z + u3.z),
                                    (u0.w + u1.w) + (u2.w + u3.w));
}

extern "C" void kernel_launch(void* const* d_in, const int* in_sizes, int n_in,
                              void* d_out, int out_size) {
    const float* rf = (const float*)d_in[0];
    const float* g  = (const float*)d_in[1];
    const float* pr = (const float*)d_in[2];
    const float* p  = (const float*)d_in[3];
    float* out = (float*)d_out;

    // Unconditional (idempotent host-side call; not a stream op, no static guard).
    cudaFuncSetAttribute(das_kernel,
                         cudaFuncAttributeMaxDynamicSharedMemorySize, SMEM_BYTES);

    pack_kernel<<<(BB * NC * NS + 255) / 256, 256>>>(rf);

    das_kernel<<<BB * PTILES * SPLIT, DTHREADS, SMEM_BYTES>>>(g, pr, p);

    combine_kernel<<<(BB * MM + 255) / 256, 256>>>(out);
}

// round 17
// speedup vs baseline: 1.7894x; 1.2585x over previous
#include <cuda_runtime.h>
#include <cuda_fp16.h>
#include <cuda_bf16.h>

#define BB 2
#define NC 128
#define NZ 256
#define NS 2048
#define NX 256
#define KK 4
#define MM (NZ * NX)

#define DTHREADS 1024
#define PXT 4                            // pixels per thread
#define PXB (DTHREADS * PXT)             // 4096 pixels per block
#define SPLIT 4                          // channel split factor
#define CHQ (NC / SPLIT)                 // 32 channels per block
#define PTILES (MM / PXB)                // 16 pixel tiles per batch
#define CHG 2                            // channels per pipeline group
#define NGRP (CHQ / CHG)                 // 16 groups per block
#define GRP_SLOTS (CHG * NS)             // uint4 slots per group: 4096 (64KB)
#define NBUF 3                           // pipeline depth
#define SMEM_BYTES (NBUF * GRP_SLOTS * 16 + NC * 16 + 16)

// fp16 PAIR-packed rf: d_rfp[(b*NC+c)*NS + s] = 8 halves {rf[s,0:4], rf[s+1,0:4]} (16B)
__device__ uint4  d_rfp[BB * NC * NS];
// Partial sums: [quarter][b][pixel] as float4
__device__ float4 d_part[SPLIT * BB * MM];

__global__ void pack_kernel(const float* __restrict__ rf) {
    const int t = blockIdx.x * blockDim.x + threadIdx.x;   // 0 .. BB*NC*NS-1
    if (t >= BB * NC * NS) return;
    const int s = t & (NS - 1);
    const float4* rf4 = (const float4*)rf;
    const float4 y0 = rf4[t];
    const float4 y1 = rf4[t + (s < NS - 1 ? 1 : 0)];
    __half2 h0 = __floats2half2_rn(y0.x, y0.y);
    __half2 h1 = __floats2half2_rn(y0.z, y0.w);
    __half2 h2 = __floats2half2_rn(y1.x, y1.y);
    __half2 h3 = __floats2half2_rn(y1.z, y1.w);
    uint4 v;
    v.x = *(unsigned*)&h0;
    v.y = *(unsigned*)&h1;
    v.z = *(unsigned*)&h2;
    v.w = *(unsigned*)&h3;
    d_rfp[t] = v;
}

__device__ __forceinline__ void cp_async16(unsigned dst_smem, const void* src) {
    asm volatile("cp.async.cg.shared.global [%0], [%1], 16;\n"
                 :: "r"(dst_smem), "l"(src));
}
#define CP_COMMIT() asm volatile("cp.async.commit_group;\n" ::: "memory")
#define CP_WAIT1()  asm volatile("cp.async.wait_group 1;\n" ::: "memory")

extern __shared__ uint4 dyn_smem[];   // [NBUF][GRP_SLOTS] buffers, pr, params

__global__ __launch_bounds__(DTHREADS, 1) void das_kernel(
    const float* __restrict__ g,    // [B, NZ, NX, 3]
    const float* __restrict__ pr,   // [B, NC, 3]
    const float* __restrict__ p)    // [B, 4]
{
    uint4*  buf  = dyn_smem;                                  // 3 x 64KB
    float4* s_pr = (float4*)(dyn_smem + NBUF * GRP_SLOTS);
    float*  s_pm = (float*)(s_pr + NC);

    const int tid  = threadIdx.x;
    const int quad = blockIdx.x & (SPLIT - 1);
    const int tile = (blockIdx.x / SPLIT) & (PTILES - 1);
    const int bb   = blockIdx.x / (SPLIT * PTILES);

    const int c0 = quad * CHQ;

    if (tid < NC) {
        const float* q = pr + ((size_t)bb * NC + tid) * 3;
        s_pr[tid] = make_float4(q[0], q[1], q[2], 0.0f);
    }
    if (tid == 0) {
        const float cc = p[bb * 4 + 0];
        const float fs = p[bb * 4 + 1];
        const float t0 = p[bb * 4 + 2];
        s_pm[0] = fs / cc;
        s_pm[1] = fs * t0 / cc;
    }

    float gx[PXT], gy[PXT], gz[PXT];
    #pragma unroll
    for (int j = 0; j < PXT; ++j) {
        const int mj = tile * PXB + j * DTHREADS + tid;
        const float* gp = g + ((size_t)bb * MM + mj) * 3;
        gx[j] = gp[0]; gy[j] = gp[1]; gz[j] = gp[2];
    }

    const uint4* __restrict__ rfg = d_rfp + ((size_t)bb * NC + c0) * NS;
    const unsigned buf_base = (unsigned)__cvta_generic_to_shared(buf);

    // Prologue: stream groups 0,1,2 into the 3 buffers.
    #pragma unroll
    for (int gpre = 0; gpre < NBUF; ++gpre) {
        const uint4* src = rfg + (size_t)gpre * GRP_SLOTS;
        const unsigned dst = buf_base + (unsigned)(gpre * GRP_SLOTS) * 16u;
        #pragma unroll
        for (int i = 0; i < 4; ++i)
            cp_async16(dst + (unsigned)(i * DTHREADS + tid) * 16u,
                       src + i * DTHREADS + tid);
        CP_COMMIT();
    }
    CP_WAIT1();        // groups 0,1 resident (this thread)
    __syncthreads();   // all threads' copies + params visible

    const float scale = s_pm[0];
    const float base  = s_pm[1];

    float4 a[PXT];
    #pragma unroll
    for (int j = 0; j < PXT; ++j) a[j] = make_float4(0.f, 0.f, 0.f, 0.f);

    int bsel = 0;                   // buffer index = grp % 3
    for (int grp = 0; grp < NGRP; ++grp) {
        const uint4* gbuf = buf + bsel * GRP_SLOTS;

        #pragma unroll
        for (int ch = 0; ch < CHG; ++ch) {
            const float4 pc = s_pr[c0 + grp * CHG + ch];
            const uint4* row = gbuf + ch * NS;

            #pragma unroll
            for (int j = 0; j < PXT; ++j) {
                const float dx = gx[j] - pc.x, dy = gy[j] - pc.y, dz = gz[j] - pc.z;
                const float r2 = fmaf(dx, dx, fmaf(dy, dy, dz * dz));
                float drx; asm("sqrt.approx.f32 %0, %1;" : "=f"(drx) : "f"(r2));
                float s = fmaf(scale, drx + gz[j], base);
                s = fminf(fmaxf(s, 0.0f), (float)(NS - 1));
                const float i0f = fminf(floorf(s), (float)(NS - 2));
                const int   i0  = (int)i0f;
                const float w  = s - i0f;
                const float wm = 1.0f - w;
                const uint4 v = row[i0];                 // ONE LDS.128: both taps
                const float2 f0 = __half22float2(*(const __half2*)&v.x);
                const float2 f1 = __half22float2(*(const __half2*)&v.y);
                const float2 f2 = __half22float2(*(const __half2*)&v.z);
                const float2 f3 = __half22float2(*(const __half2*)&v.w);
                a[j].x = fmaf(wm, f0.x, fmaf(w, f2.x, a[j].x));
                a[j].y = fmaf(wm, f0.y, fmaf(w, f2.y, a[j].y));
                a[j].z = fmaf(wm, f1.x, fmaf(w, f3.x, a[j].z));
                a[j].w = fmaf(wm, f1.y, fmaf(w, f3.y, a[j].w));
            }
        }

        // Pipeline advance: group grp+1 must be complete before next compute;
        // group grp+2 may stay in flight (wait_group 1).
        CP_WAIT1();
        __syncthreads();   // all threads done reading buf[bsel]; grp+1 visible

        if (grp + NBUF < NGRP) {
            const uint4* src = rfg + (size_t)(grp + NBUF) * GRP_SLOTS;
            const unsigned dst = buf_base + (unsigned)(bsel * GRP_SLOTS) * 16u;
            #pragma unroll
            for (int i = 0; i < 4; ++i)
                cp_async16(dst + (unsigned)(i * DTHREADS + tid) * 16u,
                           src + i * DTHREADS + tid);
        }
        CP_COMMIT();       // commit (possibly empty) to keep group counting uniform

        bsel = (bsel == NBUF - 1) ? 0 : bsel + 1;
    }

    float4* part = d_part + ((size_t)quad * BB + bb) * MM;
    #pragma unroll
    for (int j = 0; j < PXT; ++j)
        part[tile * PXB + j * DTHREADS + tid] = a[j];
}

__global__ void combine_kernel(float* __restrict__ out) {
    const int t = blockIdx.x * blockDim.x + threadIdx.x;   // 0 .. BB*MM-1
    if (t >= BB * MM) return;
    const float4 u0 = d_part[t];
    const float4 u1 = d_part[BB * MM + t];
    const float4 u2 = d_part[2 * BB * MM + t];
    const float4 u3 = d_part[3 * BB * MM + t];
    ((float4*)out)[t] = make_float4((u0.x + u1.x) + (u2.x + u3.x),
                                    (u0.y + u1.y) + (u2.y + u3.y),
                                    (u0.z + u1.z) + (u2.z + u3.z),
                                    (u0.w + u1.w) + (u2.w + u3.w));
}

extern "C" void kernel_launch(void* const* d_in, const int* in_sizes, int n_in,
                              void* d_out, int out_size) {
    const float* rf = (const float*)d_in[0];
    const float* g  = (const float*)d_in[1];
    const float* pr = (const float*)d_in[2];
    const float* p  = (const float*)d_in[3];
    float* out = (float*)d_out;

    // Unconditional (idempotent host-side call; not a stream op, no static guard).
    cudaFuncSetAttribute(das_kernel,
                         cudaFuncAttributeMaxDynamicSharedMemorySize, SMEM_BYTES);

    pack_kernel<<<(BB * NC * NS + 255) / 256, 256>>>(rf);

    das_kernel<<<BB * PTILES * SPLIT, DTHREADS, SMEM_BYTES>>>(g, pr, p);

    combine_kernel<<<(BB * MM + 255) / 256, 256>>>(out);
}